// round 14
// baseline (speedup 1.0000x reference)
#include <cuda_runtime.h>
#include <cuda_bf16.h>
#include <cstdint>

// ---------------------------------------------------------------------------
// MHC layer: LN -> Q/K/V GEMMs (mma.sync bf16 split 3-pass, cp.async) ->
// scores (8 k-splits) -> Sinkhorn(50) -> attend -> epilogue.
// B=64, N=64, D=2048.  GEMM: x = hi + lo (bf16 each);
// A@W^T ~= Ah@Wh + Ah@Wl + Al@Wh (lo*lo dropped, ~2^-16 rel), fp32 accum.
// Sinkhorn in linear domain on scaling vectors r,c (== reference log-domain).
// ---------------------------------------------------------------------------

#define BATCH 64
#define NAG   64
#define DIM   2048
#define MROWS (BATCH * NAG)      // 4096
#define NSPLIT 8

__device__ float g_normed[(size_t)MROWS * DIM];
__device__ float g_q[(size_t)MROWS * DIM];
__device__ float g_k[(size_t)MROWS * DIM];
__device__ float g_v[(size_t)MROWS * DIM];
__device__ float g_scaled[(size_t)MROWS * DIM];
__device__ float g_attn[(size_t)BATCH * NAG * NAG];
__device__ float g_spart[(size_t)BATCH * NSPLIT * NAG * NAG];
__device__ float g_ss2[(size_t)16 * MROWS];
__device__ __nv_bfloat16 g_a_hi[(size_t)MROWS * DIM];
__device__ __nv_bfloat16 g_a_lo[(size_t)MROWS * DIM];
__device__ __nv_bfloat16 g_w_hi[3][(size_t)DIM * DIM];
__device__ __nv_bfloat16 g_w_lo[3][(size_t)DIM * DIM];

__device__ __forceinline__ uint32_t s2u(const void* p) {
    uint32_t a;
    asm("{ .reg .u64 t; cvta.to.shared.u64 t, %1; cvt.u32.u64 %0, t; }"
        : "=r"(a) : "l"(p));
    return a;
}
__device__ __forceinline__ void ldsm_x4(uint32_t& r0, uint32_t& r1,
                                        uint32_t& r2, uint32_t& r3, uint32_t a) {
    asm volatile("ldmatrix.sync.aligned.m8n8.x4.shared.b16 {%0,%1,%2,%3}, [%4];"
                 : "=r"(r0), "=r"(r1), "=r"(r2), "=r"(r3) : "r"(a));
}
__device__ __forceinline__ void mma16816(float* c, const uint32_t* a,
                                         uint32_t b0, uint32_t b1) {
    asm volatile(
        "mma.sync.aligned.m16n8k16.row.col.f32.bf16.bf16.f32 "
        "{%0,%1,%2,%3}, {%4,%5,%6,%7}, {%8,%9}, {%0,%1,%2,%3};"
        : "+f"(c[0]), "+f"(c[1]), "+f"(c[2]), "+f"(c[3])
        : "r"(a[0]), "r"(a[1]), "r"(a[2]), "r"(a[3]), "r"(b0), "r"(b1));
}
__device__ __forceinline__ void cp16(uint32_t dst, const void* src) {
    asm volatile("cp.async.cg.shared.global [%0], [%1], 16;"
                 :: "r"(dst), "l"(src));
}

// ---------------------------------------------------------------------------
// 1) LayerNorm: one block per row; also emits bf16 hi/lo split.
// ---------------------------------------------------------------------------
__global__ __launch_bounds__(256) void ln_kernel(
    const float* __restrict__ x, const float* __restrict__ w, const float* __restrict__ b)
{
    const int row = blockIdx.x;
    const size_t base = (size_t)row * DIM;
    const int tid = threadIdx.x;

    float loc[8];
    float s = 0.f, sq = 0.f;
#pragma unroll
    for (int i = 0; i < 8; i++) {
        float v = x[base + tid + i * 256];
        loc[i] = v; s += v; sq += v * v;
    }
#pragma unroll
    for (int o = 16; o; o >>= 1) {
        s  += __shfl_down_sync(0xffffffffu, s,  o);
        sq += __shfl_down_sync(0xffffffffu, sq, o);
    }
    __shared__ float red[18];
    const int wid = tid >> 5, lid = tid & 31;
    if (lid == 0) { red[wid] = s; red[8 + wid] = sq; }
    __syncthreads();
    if (tid < 32) {
        float s2 = (tid < 8) ? red[tid]     : 0.f;
        float q2 = (tid < 8) ? red[8 + tid] : 0.f;
#pragma unroll
        for (int o = 4; o; o >>= 1) {
            s2 += __shfl_down_sync(0xffffffffu, s2, o);
            q2 += __shfl_down_sync(0xffffffffu, q2, o);
        }
        if (tid == 0) {
            float mu  = s2 * (1.f / (float)DIM);
            float var = q2 * (1.f / (float)DIM) - mu * mu;
            red[16] = mu;
            red[17] = rsqrtf(var + 1e-5f);
        }
    }
    __syncthreads();
    const float mu = red[16], rstd = red[17];
#pragma unroll
    for (int i = 0; i < 8; i++) {
        int c = tid + i * 256;
        float v = (loc[i] - mu) * rstd * w[c] + b[c];
        g_normed[base + c] = v;
        __nv_bfloat16 h = __float2bfloat16(v);
        g_a_hi[base + c] = h;
        g_a_lo[base + c] = __float2bfloat16(v - __bfloat162float(h));
    }
}

// ---------------------------------------------------------------------------
// 1b) Weight split: W -> hi/lo bf16
// ---------------------------------------------------------------------------
__global__ __launch_bounds__(256) void wconv_kernel(
    const float* __restrict__ wq, const float* __restrict__ wk, const float* __restrict__ wv)
{
    const int z = blockIdx.y;
    const float* __restrict__ w = (z == 0) ? wq : (z == 1) ? wk : wv;
    __nv_bfloat16* __restrict__ hi = g_w_hi[z];
    __nv_bfloat16* __restrict__ lo = g_w_lo[z];
    const size_t base = (size_t)blockIdx.x * 2048 + threadIdx.x;
#pragma unroll
    for (int i = 0; i < 8; i++) {
        size_t idx = base + (size_t)i * 256;
        float v = w[idx];
        __nv_bfloat16 h = __float2bfloat16(v);
        hi[idx] = h;
        lo[idx] = __float2bfloat16(v - __bfloat162float(h));
    }
}

// ---------------------------------------------------------------------------
// 2) mma.sync GEMM: C[4096,2048] = normed @ W^T + bias (3-pass split-bf16).
//    128x128 CTA tile, 8 warps (each 32x64), BK=32, cp.async double-buffer
//    (1 barrier per chunk).  W is [N][K] k-contiguous == mma B col-major.
// ---------------------------------------------------------------------------
#define LDP 40   // smem row stride in halves (80B) -> conflict-free ldmatrix

__global__ __launch_bounds__(256) void gemm_mma_kernel(
    const float* __restrict__ Bq, const float* __restrict__ Bk, const float* __restrict__ Bv)
{
    __shared__ __align__(16) __nv_bfloat16 Asm[2][128][LDP];
    __shared__ __align__(16) __nv_bfloat16 Bsm[2][128][LDP];

    const int tid = threadIdx.x;
    const int lane = tid & 31, wid = tid >> 5;
    const int wm = wid & 3, wn = wid >> 2;        // warp tile: rows wm*32, cols wn*64
    const int sel = blockIdx.z;
    const int rowBase = blockIdx.y * 128;
    const int colBase = blockIdx.x * 128;

    const __nv_bfloat16* __restrict__ Wh = g_w_hi[sel];
    const __nv_bfloat16* __restrict__ Wl = g_w_lo[sel];
    const float* __restrict__ bias = (sel == 0) ? Bq : (sel == 1) ? Bk : Bv;
    float* __restrict__ C = (sel == 0) ? g_q : (sel == 1) ? g_k : g_v;

    float acc[2][8][4] = {};                       // [m16][n8][frag]

    const uint32_t sbA = s2u(&Asm[0][0][0]);
    const uint32_t sbB = s2u(&Bsm[0][0][0]);
    const int arow = (lane & 15);
    const int acol = (lane >> 4) * 8;
    const int brow = ((lane >> 4) & 1) * 8 + (lane & 7);
    const int bcol = ((lane >> 3) & 1) * 8;
    const uint32_t aBase = sbA + (uint32_t)(((wm * 32 + arow) * LDP + acol) * 2);
    const uint32_t bBase = sbB + (uint32_t)(((wn * 64 + brow) * LDP + bcol) * 2);
    const uint32_t bufStride = 128 * LDP * 2;      // bytes per buffer

    // per-thread cp.async lane: r = tid>>2 (row), seg = tid&3 (16B segment)
    const int ldr = tid >> 2, lds = (tid & 3) * 8;
    const uint32_t dstA = sbA + (uint32_t)((ldr * LDP + lds) * 2);
    const uint32_t dstB = sbB + (uint32_t)((ldr * LDP + lds) * 2);
    const int ldr2 = ldr + 64;                     // second half (i=1)
    const uint32_t dstA2 = sbA + (uint32_t)((ldr2 * LDP + lds) * 2);
    const uint32_t dstB2 = sbB + (uint32_t)((ldr2 * LDP + lds) * 2);

    auto issueChunk = [&](int v, int buf) {        // v in [0, 192)
        const int pass = v >> 6;
        const size_t kof = (size_t)(v & 63) * 32 + lds;
        const __nv_bfloat16* Ap = (pass == 2) ? g_a_lo : g_a_hi;
        const __nv_bfloat16* Bp = (pass == 1) ? Wl : Wh;
        const uint32_t bo = buf * bufStride;
        cp16(dstA  + bo, Ap + (size_t)(rowBase + ldr ) * DIM + kof);
        cp16(dstA2 + bo, Ap + (size_t)(rowBase + ldr2) * DIM + kof);
        cp16(dstB  + bo, Bp + (size_t)(colBase + ldr ) * DIM + kof);
        cp16(dstB2 + bo, Bp + (size_t)(colBase + ldr2) * DIM + kof);
        asm volatile("cp.async.commit_group;");
    };

    issueChunk(0, 0);
    asm volatile("cp.async.wait_group 0;");
    __syncthreads();

    int buf = 0;
    for (int v = 0; v < 192; v++) {
        const bool more = (v + 1 < 192);
        if (more) issueChunk(v + 1, buf ^ 1);

        const uint32_t aB = aBase + buf * bufStride;
        const uint32_t bB = bBase + buf * bufStride;
#pragma unroll
        for (int kt = 0; kt < 2; kt++) {
            uint32_t bf[4][4];
#pragma unroll
            for (int g = 0; g < 4; g++)
                ldsm_x4(bf[g][0], bf[g][1], bf[g][2], bf[g][3],
                        bB + (uint32_t)((g * 16 * LDP + kt * 16) * 2));
#pragma unroll
            for (int mt = 0; mt < 2; mt++) {
                uint32_t af[4];
                ldsm_x4(af[0], af[1], af[2], af[3],
                        aB + (uint32_t)((mt * 16 * LDP + kt * 16) * 2));
#pragma unroll
                for (int g = 0; g < 4; g++) {
                    mma16816(acc[mt][g * 2 + 0], af, bf[g][0], bf[g][1]);
                    mma16816(acc[mt][g * 2 + 1], af, bf[g][2], bf[g][3]);
                }
            }
        }
        if (more) {
            asm volatile("cp.async.wait_group 0;");
            __syncthreads();
            buf ^= 1;
        }
    }

    const int r0 = rowBase + wm * 32 + (lane >> 2);
    const int c0 = colBase + wn * 64 + (lane & 3) * 2;
#pragma unroll
    for (int mt = 0; mt < 2; mt++) {
#pragma unroll
        for (int nt = 0; nt < 8; nt++) {
            const int col = c0 + nt * 8;
            const float2 bv = *(const float2*)&bias[col];
            float2 lo = make_float2(acc[mt][nt][0] + bv.x, acc[mt][nt][1] + bv.y);
            float2 hi = make_float2(acc[mt][nt][2] + bv.x, acc[mt][nt][3] + bv.y);
            *(float2*)&C[(size_t)(r0 + mt * 16) * DIM + col]     = lo;
            *(float2*)&C[(size_t)(r0 + mt * 16 + 8) * DIM + col] = hi;
        }
    }
}

// ---------------------------------------------------------------------------
// 3) scores partials: per (k-split, batch), S_part = q kT over 256 k's (f32x2).
//    8 splits for occupancy (was 4: measured occ 22%, issue 22%).
// ---------------------------------------------------------------------------
__global__ __launch_bounds__(256) void scores_kernel()
{
    __shared__ __align__(16) float2 qs[32][66];
    __shared__ __align__(16) float  ks[32][68];
    const int split = blockIdx.x;        // 0..7
    const int b = blockIdx.y;
    const int k0 = split * 256;
    const int tid = threadIdx.x;
    const int ty = tid >> 4, tx = tid & 15;
    const float* qb = g_q + (size_t)b * NAG * DIM;
    const float* kb = g_k + (size_t)b * NAG * DIM;

    unsigned long long acc[4][2] = {};
    for (int kt = 0; kt < 256; kt += 32) {
        __syncthreads();
#pragma unroll
        for (int i = 0; i < 2; i++) {
            int idx = tid + i * 256;
            int r = idx >> 3, cg = (idx & 7) << 2;
            float4 vq = *(const float4*)&qb[(size_t)r * DIM + k0 + kt + cg];
            float4 vk = *(const float4*)&kb[(size_t)r * DIM + k0 + kt + cg];
            qs[cg + 0][r] = make_float2(vq.x, vq.x);
            qs[cg + 1][r] = make_float2(vq.y, vq.y);
            qs[cg + 2][r] = make_float2(vq.z, vq.z);
            qs[cg + 3][r] = make_float2(vq.w, vq.w);
            ks[cg + 0][r] = vk.x; ks[cg + 1][r] = vk.y;
            ks[cg + 2][r] = vk.z; ks[cg + 3][r] = vk.w;
        }
        __syncthreads();
#pragma unroll
        for (int kk = 0; kk < 32; kk++) {
            const ulonglong2* ap = (const ulonglong2*)&qs[kk][ty * 4];
            ulonglong2 a01 = ap[0], a23 = ap[1];
            ulonglong2 bp  = *(const ulonglong2*)&ks[kk][tx * 4];
            unsigned long long ad[4] = {a01.x, a01.y, a23.x, a23.y};
            unsigned long long bb[2] = {bp.x, bp.y};
#pragma unroll
            for (int i = 0; i < 4; i++)
#pragma unroll
                for (int j = 0; j < 2; j++)
                    asm("fma.rn.f32x2 %0, %1, %2, %0;"
                        : "+l"(acc[i][j]) : "l"(ad[i]), "l"(bb[j]));
        }
    }
    const size_t base = ((size_t)b * NSPLIT + split) * (NAG * NAG);
#pragma unroll
    for (int i = 0; i < 4; i++) {
        float2 p0 = *(float2*)&acc[i][0];
        float2 p1 = *(float2*)&acc[i][1];
        *(float4*)&g_spart[base + (ty * 4 + i) * NAG + tx * 4] =
            make_float4(p0.x, p0.y, p1.x, p1.y);
    }
}

// ---------------------------------------------------------------------------
// 4) Sinkhorn (fused split-reduce + exp).  Linear domain == reference log-domain.
// ---------------------------------------------------------------------------
__global__ __launch_bounds__(64) void sinkhorn_kernel(float* __restrict__ attn_out)
{
    __shared__ float Ks[64][65];
    __shared__ float rv[64], cv[64];
    const int b = blockIdx.x, t = threadIdx.x;
    const size_t base  = (size_t)b * (NAG * NAG);
    const size_t pbase = (size_t)b * NSPLIT * (NAG * NAG);
    const float kscale = 0.022097086912079608f;   // 1/sqrt(2048)

#pragma unroll 4
    for (int n = 0; n < 64; n++) {
        float s = 0.f;
#pragma unroll
        for (int sp = 0; sp < NSPLIT; sp++)
            s += g_spart[pbase + (size_t)sp * (NAG * NAG) + n * 64 + t];
        Ks[n][t] = expf(s * kscale);
    }
    cv[t] = 1.f;
    __syncthreads();

    for (int it = 0; it < 50; it++) {
        float s0 = 0.f, s1 = 0.f;
#pragma unroll 8
        for (int m = 0; m < 32; m++) {
            s0 = fmaf(Ks[t][m],      cv[m],      s0);
            s1 = fmaf(Ks[t][m + 32], cv[m + 32], s1);
        }
        rv[t] = 1.f / (s0 + s1);
        __syncthreads();
        float u0 = 0.f, u1 = 0.f;
#pragma unroll 8
        for (int n = 0; n < 32; n++) {
            u0 = fmaf(Ks[n][t],      rv[n],      u0);
            u1 = fmaf(Ks[n + 32][t], rv[n + 32], u1);
        }
        cv[t] = 1.f / (u0 + u1);
        __syncthreads();
    }

#pragma unroll 8
    for (int n = 0; n < 64; n++) {
        float v = rv[n] * Ks[n][t] * cv[t];
        g_attn[base + n * 64 + t] = v;
        if (attn_out) attn_out[base + n * 64 + t] = v;
    }
}

// ---------------------------------------------------------------------------
// 5) attended = attn @ v + mix/bias/scale (f32x2); per-row sumsq partials
// ---------------------------------------------------------------------------
__global__ __launch_bounds__(256) void attend_kernel(
    const float* __restrict__ biases, const float* __restrict__ scalef)
{
    __shared__ float2 Asm2[64][65];
    __shared__ __align__(16) float Vs[64][128];
    const int dt = blockIdx.x;
    const int b = blockIdx.y;
    const int d0 = dt * 128;
    const int tid = threadIdx.x;
    const int tn = tid >> 5;
    const int td = tid & 31;

#pragma unroll
    for (int i = 0; i < 16; i++) {
        int idx = tid + i * 256;
        float v = g_attn[(size_t)b * (NAG * NAG) + idx];
        Asm2[idx >> 6][idx & 63] = make_float2(v, v);
    }
#pragma unroll
    for (int i = 0; i < 8; i++) {
        int idx = tid + i * 256;
        int r = idx >> 5, cg = (idx & 31) << 2;
        *(float4*)&Vs[r][cg] =
            *(const float4*)&g_v[((size_t)b * NAG + r) * DIM + d0 + cg];
    }
    __syncthreads();

    unsigned long long acc[8][2] = {};
#pragma unroll 4
    for (int m = 0; m < 64; m++) {
        ulonglong2 vp = *(const ulonglong2*)&Vs[m][td * 4];
#pragma unroll
        for (int i = 0; i < 8; i++) {
            unsigned long long ad =
                *(const unsigned long long*)&Asm2[tn + i * 8][m];
            asm("fma.rn.f32x2 %0, %1, %2, %0;"
                : "+l"(acc[i][0]) : "l"(ad), "l"(vp.x));
            asm("fma.rn.f32x2 %0, %1, %2, %0;"
                : "+l"(acc[i][1]) : "l"(ad), "l"(vp.y));
        }
    }

#pragma unroll
    for (int i = 0; i < 8; i++) {
        const int n = tn + i * 8;
        const size_t rg = (size_t)b * NAG + n;
        const size_t off = rg * DIM + d0 + td * 4;
        const float4 nm = *(const float4*)&g_normed[off];
        const float4 bb = *(const float4*)&biases[(size_t)n * DIM + d0 + td * 4];
        const float sfv = scalef[n];
        float2 p0 = *(float2*)&acc[i][0];
        float2 p1 = *(float2*)&acc[i][1];
        float4 o;
        o.x = (0.1f * nm.x + 0.9f * p0.x + bb.x) * sfv;
        o.y = (0.1f * nm.y + 0.9f * p0.y + bb.y) * sfv;
        o.z = (0.1f * nm.z + 0.9f * p1.x + bb.z) * sfv;
        o.w = (0.1f * nm.w + 0.9f * p1.y + bb.w) * sfv;
        *(float4*)&g_scaled[off] = o;
        float p = o.x * o.x + o.y * o.y + o.z * o.z + o.w * o.w;
#pragma unroll
        for (int o2 = 16; o2; o2 >>= 1) p += __shfl_down_sync(0xffffffffu, p, o2);
        if (td == 0) g_ss2[(size_t)dt * MROWS + rg] = p;
    }
}

// ---------------------------------------------------------------------------
// 6) final: norm clamp + residual
// ---------------------------------------------------------------------------
__global__ __launch_bounds__(256) void final_kernel(
    const float* __restrict__ x, float* __restrict__ out)
{
    const int row = blockIdx.x;
    float ssum = 0.f;
#pragma unroll
    for (int t2 = 0; t2 < 16; t2++) ssum += g_ss2[(size_t)t2 * MROWS + row];
    const float inv = 1.f / fmaxf(1.f, sqrtf(ssum));
    const size_t base = (size_t)row * DIM;
#pragma unroll
    for (int i = 0; i < 8; i++) {
        int c = threadIdx.x + i * 256;
        out[base + c] = x[base + c] + g_scaled[base + c] * inv;
    }
}

// ---------------------------------------------------------------------------
extern "C" void kernel_launch(void* const* d_in, const int* in_sizes, int n_in,
                              void* d_out, int out_size)
{
    const float* x   = (const float*)d_in[0];
    const float* lnw = (const float*)d_in[1];
    const float* lnb = (const float*)d_in[2];
    const float* wq  = (const float*)d_in[3];
    const float* bq  = (const float*)d_in[4];
    const float* wk  = (const float*)d_in[5];
    const float* bk  = (const float*)d_in[6];
    const float* wv  = (const float*)d_in[7];
    const float* bv  = (const float*)d_in[8];
    const float* ab  = (const float*)d_in[9];
    const float* sf  = (const float*)d_in[10];
    float* out = (float*)d_out;

    const int OUT_ELEMS  = MROWS * DIM;          // 8388608
    const int ATTN_ELEMS = BATCH * NAG * NAG;    // 262144

    float* attn_out = nullptr;
    float* out_main = nullptr;
    if (out_size >= OUT_ELEMS + ATTN_ELEMS) { out_main = out; attn_out = out + OUT_ELEMS; }
    else if (out_size >= OUT_ELEMS)          { out_main = out; }
    else if (out_size >= ATTN_ELEMS)         { attn_out = out; }

    ln_kernel<<<MROWS, 256>>>(x, lnw, lnb);
    wconv_kernel<<<dim3(2048, 3), 256>>>(wq, wk, wv);
    gemm_mma_kernel<<<dim3(16, 32, 3), 256>>>(bq, bk, bv);
    scores_kernel<<<dim3(NSPLIT, 64), 256>>>();
    sinkhorn_kernel<<<64, 64>>>(attn_out);
    attend_kernel<<<dim3(16, 64), 256>>>(ab, sf);
    if (out_main) final_kernel<<<MROWS, 256>>>(x, out_main);
}

// round 16
// speedup vs baseline: 1.2896x; 1.2896x over previous
#include <cuda_runtime.h>
#include <cuda_bf16.h>
#include <cstdint>

// ---------------------------------------------------------------------------
// MHC layer: LN -> Q/K/V GEMMs (mma.sync bf16 split 3-pass) -> scores
// (8 k-splits) -> Sinkhorn(50) -> attend -> epilogue.  B=64, N=64, D=2048.
// GEMM: x = hi + lo (bf16 each); A@W^T ~= Ah@Wh + Ah@Wl + Al@Wh (lo*lo
// dropped, ~2^-16 rel), fp32 accum.  Register-staged double buffer with a
// SINGLE barrier per chunk (the second barrier of the R12 version is
// provably redundant).  cp.async reverted: measured regression (+320us).
// Sinkhorn in linear domain on scaling vectors r,c (== reference log-domain).
// ---------------------------------------------------------------------------

#define BATCH 64
#define NAG   64
#define DIM   2048
#define MROWS (BATCH * NAG)      // 4096
#define NSPLIT 8

__device__ float g_normed[(size_t)MROWS * DIM];
__device__ float g_q[(size_t)MROWS * DIM];
__device__ float g_k[(size_t)MROWS * DIM];
__device__ float g_v[(size_t)MROWS * DIM];
__device__ float g_scaled[(size_t)MROWS * DIM];
__device__ float g_attn[(size_t)BATCH * NAG * NAG];
__device__ float g_spart[(size_t)BATCH * NSPLIT * NAG * NAG];
__device__ float g_ss2[(size_t)16 * MROWS];
__device__ __nv_bfloat16 g_a_hi[(size_t)MROWS * DIM];
__device__ __nv_bfloat16 g_a_lo[(size_t)MROWS * DIM];
__device__ __nv_bfloat16 g_w_hi[3][(size_t)DIM * DIM];
__device__ __nv_bfloat16 g_w_lo[3][(size_t)DIM * DIM];

__device__ __forceinline__ uint32_t s2u(const void* p) {
    uint32_t a;
    asm("{ .reg .u64 t; cvta.to.shared.u64 t, %1; cvt.u32.u64 %0, t; }"
        : "=r"(a) : "l"(p));
    return a;
}
__device__ __forceinline__ void ldsm_x4(uint32_t& r0, uint32_t& r1,
                                        uint32_t& r2, uint32_t& r3, uint32_t a) {
    asm volatile("ldmatrix.sync.aligned.m8n8.x4.shared.b16 {%0,%1,%2,%3}, [%4];"
                 : "=r"(r0), "=r"(r1), "=r"(r2), "=r"(r3) : "r"(a));
}
__device__ __forceinline__ void mma16816(float* c, const uint32_t* a,
                                         uint32_t b0, uint32_t b1) {
    asm volatile(
        "mma.sync.aligned.m16n8k16.row.col.f32.bf16.bf16.f32 "
        "{%0,%1,%2,%3}, {%4,%5,%6,%7}, {%8,%9}, {%0,%1,%2,%3};"
        : "+f"(c[0]), "+f"(c[1]), "+f"(c[2]), "+f"(c[3])
        : "r"(a[0]), "r"(a[1]), "r"(a[2]), "r"(a[3]), "r"(b0), "r"(b1));
}

// ---------------------------------------------------------------------------
// 1) LayerNorm: one block per row; also emits bf16 hi/lo split.
// ---------------------------------------------------------------------------
__global__ __launch_bounds__(256) void ln_kernel(
    const float* __restrict__ x, const float* __restrict__ w, const float* __restrict__ b)
{
    const int row = blockIdx.x;
    const size_t base = (size_t)row * DIM;
    const int tid = threadIdx.x;

    float loc[8];
    float s = 0.f, sq = 0.f;
#pragma unroll
    for (int i = 0; i < 8; i++) {
        float v = x[base + tid + i * 256];
        loc[i] = v; s += v; sq += v * v;
    }
#pragma unroll
    for (int o = 16; o; o >>= 1) {
        s  += __shfl_down_sync(0xffffffffu, s,  o);
        sq += __shfl_down_sync(0xffffffffu, sq, o);
    }
    __shared__ float red[18];
    const int wid = tid >> 5, lid = tid & 31;
    if (lid == 0) { red[wid] = s; red[8 + wid] = sq; }
    __syncthreads();
    if (tid < 32) {
        float s2 = (tid < 8) ? red[tid]     : 0.f;
        float q2 = (tid < 8) ? red[8 + tid] : 0.f;
#pragma unroll
        for (int o = 4; o; o >>= 1) {
            s2 += __shfl_down_sync(0xffffffffu, s2, o);
            q2 += __shfl_down_sync(0xffffffffu, q2, o);
        }
        if (tid == 0) {
            float mu  = s2 * (1.f / (float)DIM);
            float var = q2 * (1.f / (float)DIM) - mu * mu;
            red[16] = mu;
            red[17] = rsqrtf(var + 1e-5f);
        }
    }
    __syncthreads();
    const float mu = red[16], rstd = red[17];
#pragma unroll
    for (int i = 0; i < 8; i++) {
        int c = tid + i * 256;
        float v = (loc[i] - mu) * rstd * w[c] + b[c];
        g_normed[base + c] = v;
        __nv_bfloat16 h = __float2bfloat16(v);
        g_a_hi[base + c] = h;
        g_a_lo[base + c] = __float2bfloat16(v - __bfloat162float(h));
    }
}

// ---------------------------------------------------------------------------
// 1b) Weight split: W -> hi/lo bf16
// ---------------------------------------------------------------------------
__global__ __launch_bounds__(256) void wconv_kernel(
    const float* __restrict__ wq, const float* __restrict__ wk, const float* __restrict__ wv)
{
    const int z = blockIdx.y;
    const float* __restrict__ w = (z == 0) ? wq : (z == 1) ? wk : wv;
    __nv_bfloat16* __restrict__ hi = g_w_hi[z];
    __nv_bfloat16* __restrict__ lo = g_w_lo[z];
    const size_t base = (size_t)blockIdx.x * 2048 + threadIdx.x;
#pragma unroll
    for (int i = 0; i < 8; i++) {
        size_t idx = base + (size_t)i * 256;
        float v = w[idx];
        __nv_bfloat16 h = __float2bfloat16(v);
        hi[idx] = h;
        lo[idx] = __float2bfloat16(v - __bfloat162float(h));
    }
}

// ---------------------------------------------------------------------------
// 2) mma.sync GEMM: C[4096,2048] = normed @ W^T + bias (3-pass split-bf16).
//    128x128 CTA tile, 8 warps (each 32x64), BK=32, register-staged double
//    buffer, ONE barrier per chunk.  W is [N][K] k-contig == mma B col-major.
// ---------------------------------------------------------------------------
#define LDP 40   // smem row stride in halves (80B) -> conflict-free ldmatrix

__global__ __launch_bounds__(256) void gemm_mma_kernel(
    const float* __restrict__ Bq, const float* __restrict__ Bk, const float* __restrict__ Bv)
{
    __shared__ __align__(16) __nv_bfloat16 Asm[2][128][LDP];
    __shared__ __align__(16) __nv_bfloat16 Bsm[2][128][LDP];

    const int tid = threadIdx.x;
    const int lane = tid & 31, wid = tid >> 5;
    const int wm = wid & 3, wn = wid >> 2;        // warp tile: rows wm*32, cols wn*64
    const int sel = blockIdx.z;
    const int rowBase = blockIdx.y * 128;
    const int colBase = blockIdx.x * 128;

    const __nv_bfloat16* __restrict__ Wh = g_w_hi[sel];
    const __nv_bfloat16* __restrict__ Wl = g_w_lo[sel];
    const float* __restrict__ bias = (sel == 0) ? Bq : (sel == 1) ? Bk : Bv;
    float* __restrict__ C = (sel == 0) ? g_q : (sel == 1) ? g_k : g_v;

    float acc[2][8][4] = {};                       // [m16][n8][frag]

    const uint32_t sbA = s2u(&Asm[0][0][0]);
    const uint32_t sbB = s2u(&Bsm[0][0][0]);
    const int arow = (lane & 15);
    const int acol = (lane >> 4) * 8;
    const int brow = ((lane >> 4) & 1) * 8 + (lane & 7);
    const int bcol = ((lane >> 3) & 1) * 8;
    const uint32_t aBase = sbA + (uint32_t)(((wm * 32 + arow) * LDP + acol) * 2);
    const uint32_t bBase = sbB + (uint32_t)(((wn * 64 + brow) * LDP + bcol) * 2);
    const uint32_t bufStride = 128 * LDP * 2;      // bytes per buffer

    uint4 pa[2], pb[2];
    auto loadChunk = [&](int v) {                  // v in [0, 192)
        const int pass = v >> 6;
        const size_t kof = (size_t)(v & 63) * 32;
        const __nv_bfloat16* Ap = (pass == 2) ? g_a_lo : g_a_hi;
        const __nv_bfloat16* Bp = (pass == 1) ? Wl : Wh;
#pragma unroll
        for (int i = 0; i < 2; i++) {
            const int idx = tid + i * 256;
            const int r = idx >> 2, seg = idx & 3;
            pa[i] = *(const uint4*)&Ap[(size_t)(rowBase + r) * DIM + kof + seg * 8];
            pb[i] = *(const uint4*)&Bp[(size_t)(colBase + r) * DIM + kof + seg * 8];
        }
    };
    auto storeChunk = [&](int buf) {
#pragma unroll
        for (int i = 0; i < 2; i++) {
            const int idx = tid + i * 256;
            const int r = idx >> 2, seg = idx & 3;
            *(uint4*)&Asm[buf][r][seg * 8] = pa[i];
            *(uint4*)&Bsm[buf][r][seg * 8] = pb[i];
        }
    };

    loadChunk(0);
    storeChunk(0);
    __syncthreads();

    int buf = 0;
    for (int v = 0; v < 192; v++) {
        const bool more = (v + 1 < 192);
        if (more) loadChunk(v + 1);

        const uint32_t aB = aBase + buf * bufStride;
        const uint32_t bB = bBase + buf * bufStride;
#pragma unroll
        for (int kt = 0; kt < 2; kt++) {
            uint32_t bf[4][4];
#pragma unroll
            for (int g = 0; g < 4; g++)
                ldsm_x4(bf[g][0], bf[g][1], bf[g][2], bf[g][3],
                        bB + (uint32_t)((g * 16 * LDP + kt * 16) * 2));
#pragma unroll
            for (int mt = 0; mt < 2; mt++) {
                uint32_t af[4];
                ldsm_x4(af[0], af[1], af[2], af[3],
                        aB + (uint32_t)((mt * 16 * LDP + kt * 16) * 2));
#pragma unroll
                for (int g = 0; g < 4; g++) {
                    mma16816(acc[mt][g * 2 + 0], af, bf[g][0], bf[g][1]);
                    mma16816(acc[mt][g * 2 + 1], af, bf[g][2], bf[g][3]);
                }
            }
        }
        if (more) {
            // Store next chunk into buf^1.  Safe without a pre-store barrier:
            // all reads of buf^1 occurred in compute(v-1), which precedes the
            // post-store barrier of iteration v-1 for every warp.
            storeChunk(buf ^ 1);
            __syncthreads();
            buf ^= 1;
        }
    }

    const int r0 = rowBase + wm * 32 + (lane >> 2);
    const int c0 = colBase + wn * 64 + (lane & 3) * 2;
#pragma unroll
    for (int mt = 0; mt < 2; mt++) {
#pragma unroll
        for (int nt = 0; nt < 8; nt++) {
            const int col = c0 + nt * 8;
            const float2 bv = *(const float2*)&bias[col];
            float2 lo = make_float2(acc[mt][nt][0] + bv.x, acc[mt][nt][1] + bv.y);
            float2 hi = make_float2(acc[mt][nt][2] + bv.x, acc[mt][nt][3] + bv.y);
            *(float2*)&C[(size_t)(r0 + mt * 16) * DIM + col]     = lo;
            *(float2*)&C[(size_t)(r0 + mt * 16 + 8) * DIM + col] = hi;
        }
    }
}

// ---------------------------------------------------------------------------
// 3) scores partials: per (k-split, batch), S_part = q kT over 256 k's (f32x2)
// ---------------------------------------------------------------------------
__global__ __launch_bounds__(256) void scores_kernel()
{
    __shared__ __align__(16) float2 qs[32][66];
    __shared__ __align__(16) float  ks[32][68];
    const int split = blockIdx.x;        // 0..7
    const int b = blockIdx.y;
    const int k0 = split * 256;
    const int tid = threadIdx.x;
    const int ty = tid >> 4, tx = tid & 15;
    const float* qb = g_q + (size_t)b * NAG * DIM;
    const float* kb = g_k + (size_t)b * NAG * DIM;

    unsigned long long acc[4][2] = {};
    for (int kt = 0; kt < 256; kt += 32) {
        __syncthreads();
#pragma unroll
        for (int i = 0; i < 2; i++) {
            int idx = tid + i * 256;
            int r = idx >> 3, cg = (idx & 7) << 2;
            float4 vq = *(const float4*)&qb[(size_t)r * DIM + k0 + kt + cg];
            float4 vk = *(const float4*)&kb[(size_t)r * DIM + k0 + kt + cg];
            qs[cg + 0][r] = make_float2(vq.x, vq.x);
            qs[cg + 1][r] = make_float2(vq.y, vq.y);
            qs[cg + 2][r] = make_float2(vq.z, vq.z);
            qs[cg + 3][r] = make_float2(vq.w, vq.w);
            ks[cg + 0][r] = vk.x; ks[cg + 1][r] = vk.y;
            ks[cg + 2][r] = vk.z; ks[cg + 3][r] = vk.w;
        }
        __syncthreads();
#pragma unroll
        for (int kk = 0; kk < 32; kk++) {
            const ulonglong2* ap = (const ulonglong2*)&qs[kk][ty * 4];
            ulonglong2 a01 = ap[0], a23 = ap[1];
            ulonglong2 bp  = *(const ulonglong2*)&ks[kk][tx * 4];
            unsigned long long ad[4] = {a01.x, a01.y, a23.x, a23.y};
            unsigned long long bb[2] = {bp.x, bp.y};
#pragma unroll
            for (int i = 0; i < 4; i++)
#pragma unroll
                for (int j = 0; j < 2; j++)
                    asm("fma.rn.f32x2 %0, %1, %2, %0;"
                        : "+l"(acc[i][j]) : "l"(ad[i]), "l"(bb[j]));
        }
    }
    const size_t base = ((size_t)b * NSPLIT + split) * (NAG * NAG);
#pragma unroll
    for (int i = 0; i < 4; i++) {
        float2 p0 = *(float2*)&acc[i][0];
        float2 p1 = *(float2*)&acc[i][1];
        *(float4*)&g_spart[base + (ty * 4 + i) * NAG + tx * 4] =
            make_float4(p0.x, p0.y, p1.x, p1.y);
    }
}

// ---------------------------------------------------------------------------
// 4) Sinkhorn (fused split-reduce + exp).  Linear domain == reference log-domain.
// ---------------------------------------------------------------------------
__global__ __launch_bounds__(64) void sinkhorn_kernel(float* __restrict__ attn_out)
{
    __shared__ float Ks[64][65];
    __shared__ float rv[64], cv[64];
    const int b = blockIdx.x, t = threadIdx.x;
    const size_t base  = (size_t)b * (NAG * NAG);
    const size_t pbase = (size_t)b * NSPLIT * (NAG * NAG);
    const float kscale = 0.022097086912079608f;   // 1/sqrt(2048)

#pragma unroll 4
    for (int n = 0; n < 64; n++) {
        float s = 0.f;
#pragma unroll
        for (int sp = 0; sp < NSPLIT; sp++)
            s += g_spart[pbase + (size_t)sp * (NAG * NAG) + n * 64 + t];
        Ks[n][t] = expf(s * kscale);
    }
    cv[t] = 1.f;
    __syncthreads();

    for (int it = 0; it < 50; it++) {
        float s0 = 0.f, s1 = 0.f;
#pragma unroll 8
        for (int m = 0; m < 32; m++) {
            s0 = fmaf(Ks[t][m],      cv[m],      s0);
            s1 = fmaf(Ks[t][m + 32], cv[m + 32], s1);
        }
        rv[t] = 1.f / (s0 + s1);
        __syncthreads();
        float u0 = 0.f, u1 = 0.f;
#pragma unroll 8
        for (int n = 0; n < 32; n++) {
            u0 = fmaf(Ks[n][t],      rv[n],      u0);
            u1 = fmaf(Ks[n + 32][t], rv[n + 32], u1);
        }
        cv[t] = 1.f / (u0 + u1);
        __syncthreads();
    }

#pragma unroll 8
    for (int n = 0; n < 64; n++) {
        float v = rv[n] * Ks[n][t] * cv[t];
        g_attn[base + n * 64 + t] = v;
        if (attn_out) attn_out[base + n * 64 + t] = v;
    }
}

// ---------------------------------------------------------------------------
// 5) attended = attn @ v + mix/bias/scale (f32x2); per-row sumsq partials
// ---------------------------------------------------------------------------
__global__ __launch_bounds__(256) void attend_kernel(
    const float* __restrict__ biases, const float* __restrict__ scalef)
{
    __shared__ float2 Asm2[64][65];
    __shared__ __align__(16) float Vs[64][128];
    const int dt = blockIdx.x;
    const int b = blockIdx.y;
    const int d0 = dt * 128;
    const int tid = threadIdx.x;
    const int tn = tid >> 5;
    const int td = tid & 31;

#pragma unroll
    for (int i = 0; i < 16; i++) {
        int idx = tid + i * 256;
        float v = g_attn[(size_t)b * (NAG * NAG) + idx];
        Asm2[idx >> 6][idx & 63] = make_float2(v, v);
    }
#pragma unroll
    for (int i = 0; i < 8; i++) {
        int idx = tid + i * 256;
        int r = idx >> 5, cg = (idx & 31) << 2;
        *(float4*)&Vs[r][cg] =
            *(const float4*)&g_v[((size_t)b * NAG + r) * DIM + d0 + cg];
    }
    __syncthreads();

    unsigned long long acc[8][2] = {};
#pragma unroll 4
    for (int m = 0; m < 64; m++) {
        ulonglong2 vp = *(const ulonglong2*)&Vs[m][td * 4];
#pragma unroll
        for (int i = 0; i < 8; i++) {
            unsigned long long ad =
                *(const unsigned long long*)&Asm2[tn + i * 8][m];
            asm("fma.rn.f32x2 %0, %1, %2, %0;"
                : "+l"(acc[i][0]) : "l"(ad), "l"(vp.x));
            asm("fma.rn.f32x2 %0, %1, %2, %0;"
                : "+l"(acc[i][1]) : "l"(ad), "l"(vp.y));
        }
    }

#pragma unroll
    for (int i = 0; i < 8; i++) {
        const int n = tn + i * 8;
        const size_t rg = (size_t)b * NAG + n;
        const size_t off = rg * DIM + d0 + td * 4;
        const float4 nm = *(const float4*)&g_normed[off];
        const float4 bb = *(const float4*)&biases[(size_t)n * DIM + d0 + td * 4];
        const float sfv = scalef[n];
        float2 p0 = *(float2*)&acc[i][0];
        float2 p1 = *(float2*)&acc[i][1];
        float4 o;
        o.x = (0.1f * nm.x + 0.9f * p0.x + bb.x) * sfv;
        o.y = (0.1f * nm.y + 0.9f * p0.y + bb.y) * sfv;
        o.z = (0.1f * nm.z + 0.9f * p1.x + bb.z) * sfv;
        o.w = (0.1f * nm.w + 0.9f * p1.y + bb.w) * sfv;
        *(float4*)&g_scaled[off] = o;
        float p = o.x * o.x + o.y * o.y + o.z * o.z + o.w * o.w;
#pragma unroll
        for (int o2 = 16; o2; o2 >>= 1) p += __shfl_down_sync(0xffffffffu, p, o2);
        if (td == 0) g_ss2[(size_t)dt * MROWS + rg] = p;
    }
}

// ---------------------------------------------------------------------------
// 6) final: norm clamp + residual
// ---------------------------------------------------------------------------
__global__ __launch_bounds__(256) void final_kernel(
    const float* __restrict__ x, float* __restrict__ out)
{
    const int row = blockIdx.x;
    float ssum = 0.f;
#pragma unroll
    for (int t2 = 0; t2 < 16; t2++) ssum += g_ss2[(size_t)t2 * MROWS + row];
    const float inv = 1.f / fmaxf(1.f, sqrtf(ssum));
    const size_t base = (size_t)row * DIM;
#pragma unroll
    for (int i = 0; i < 8; i++) {
        int c = threadIdx.x + i * 256;
        out[base + c] = x[base + c] + g_scaled[base + c] * inv;
    }
}

// ---------------------------------------------------------------------------
extern "C" void kernel_launch(void* const* d_in, const int* in_sizes, int n_in,
                              void* d_out, int out_size)
{
    const float* x   = (const float*)d_in[0];
    const float* lnw = (const float*)d_in[1];
    const float* lnb = (const float*)d_in[2];
    const float* wq  = (const float*)d_in[3];
    const float* bq  = (const float*)d_in[4];
    const float* wk  = (const float*)d_in[5];
    const float* bk  = (const float*)d_in[6];
    const float* wv  = (const float*)d_in[7];
    const float* bv  = (const float*)d_in[8];
    const float* ab  = (const float*)d_in[9];
    const float* sf  = (const float*)d_in[10];
    float* out = (float*)d_out;

    const int OUT_ELEMS  = MROWS * DIM;          // 8388608
    const int ATTN_ELEMS = BATCH * NAG * NAG;    // 262144

    float* attn_out = nullptr;
    float* out_main = nullptr;
    if (out_size >= OUT_ELEMS + ATTN_ELEMS) { out_main = out; attn_out = out + OUT_ELEMS; }
    else if (out_size >= OUT_ELEMS)          { out_main = out; }
    else if (out_size >= ATTN_ELEMS)         { attn_out = out; }

    ln_kernel<<<MROWS, 256>>>(x, lnw, lnb);
    wconv_kernel<<<dim3(2048, 3), 256>>>(wq, wk, wv);
    gemm_mma_kernel<<<dim3(16, 32, 3), 256>>>(bq, bk, bv);
    scores_kernel<<<dim3(NSPLIT, 64), 256>>>();
    sinkhorn_kernel<<<64, 64>>>(attn_out);
    attend_kernel<<<dim3(16, 64), 256>>>(ab, sf);
    if (out_main) final_kernel<<<MROWS, 256>>>(x, out_main);
}